// round 1
// baseline (speedup 1.0000x reference)
#include <cuda_runtime.h>
#include <math.h>

#define KP 8192
#define TT 4096
#define NTHREADS 512
#define EPT 16   // elements per thread: 512*16 = 8192

// 128MB scratch: transposed z, zc[t][k] = z[k][t]
__device__ float g_zc[(size_t)TT * KP];

// ---------------------------------------------------------------------------
// Tiled transpose: z [K, T] -> g_zc [T, K], fully coalesced both sides.
// ---------------------------------------------------------------------------
__global__ void transpose_kernel(const float* __restrict__ z) {
    __shared__ float tile[32][33];
    const int t0 = blockIdx.x * 32;
    const int k0 = blockIdx.y * 32;
    const int tx = threadIdx.x, ty = threadIdx.y;  // block (32, 8)
#pragma unroll
    for (int i = 0; i < 32; i += 8)
        tile[ty + i][tx] = z[(size_t)(k0 + ty + i) * TT + (t0 + tx)];
    __syncthreads();
#pragma unroll
    for (int i = 0; i < 32; i += 8)
        g_zc[(size_t)(t0 + ty + i) * KP + (k0 + tx)] = tile[tx][ty + i];
}

// ---------------------------------------------------------------------------
// Persistent single-block SMC kernel. One SM, all state in SMEM/registers.
// Shared layout (dynamic):
//   sw   [8192] float  : current particle values w
//   scdf [8192] float  : unnormalized inclusive cumsum of exp(lw - max)
//   sb   [8192] ushort : bucket -> first cdf index covering bucket start
//   sred [96]   float  : reduction scratch (warp partials, excl offsets,
//                        [64]=block max, [65]=total)
// ---------------------------------------------------------------------------
extern __shared__ float smem_f[];

__global__ __launch_bounds__(NTHREADS, 1)
void smc_kernel(const float* __restrict__ x, const float* __restrict__ w0,
                const float* __restrict__ u, float* __restrict__ out) {
    float* sw = smem_f;                                   // KP floats
    float* scdf = sw + KP;                                // KP floats
    unsigned short* sb = (unsigned short*)(scdf + KP);    // KP ushorts
    float* sred = (float*)(sb + KP);                      // 96 floats

    const int tid = threadIdx.x;
    const int lane = tid & 31;
    const int wid = tid >> 5;
    const int kbase = tid * EPT;

    // Load initial particles: registers + shared copy (shared only for gather).
    float wr[EPT];
    {
        const float4* w4 = (const float4*)(w0 + kbase);
#pragma unroll
        for (int q = 0; q < EPT / 4; q++) {
            float4 v = w4[q];
            wr[4*q+0] = v.x; wr[4*q+1] = v.y; wr[4*q+2] = v.z; wr[4*q+3] = v.w;
        }
    }
#pragma unroll
    for (int j = 0; j < EPT; j++) sw[kbase + j] = wr[j];
    // (visible to other threads before first gather: several barriers intervene)

    double acc = 0.0;

    for (int t = 0; t < TT; t++) {
        const float xt = x[t];

        // Issue u loads early (needed only in search phase) to hide latency.
        float uv[EPT];
        {
            const float4* u4 = (const float4*)(u + (size_t)t * KP + kbase);
#pragma unroll
            for (int q = 0; q < EPT / 4; q++) {
                float4 v = u4[q];
                uv[4*q+0] = v.x; uv[4*q+1] = v.y; uv[4*q+2] = v.z; uv[4*q+3] = v.w;
            }
        }

        // lw[k] = x*z - 0.5*(z-w)^2   (per-step constant hoisted into lme)
        float zv[EPT];
        {
            const float4* z4 = (const float4*)(g_zc + (size_t)t * KP + kbase);
#pragma unroll
            for (int q = 0; q < EPT / 4; q++) {
                float4 v = z4[q];
                zv[4*q+0] = v.x; zv[4*q+1] = v.y; zv[4*q+2] = v.z; zv[4*q+3] = v.w;
            }
        }
        float lw[EPT];
        float mx = -1e30f;
#pragma unroll
        for (int j = 0; j < EPT; j++) {
            float d = zv[j] - wr[j];
            float v = fmaf(xt, zv[j], -0.5f * d * d);
            lw[j] = v;
            mx = fmaxf(mx, v);
        }

        // ---- block max reduce -------------------------------------------
#pragma unroll
        for (int o = 16; o; o >>= 1)
            mx = fmaxf(mx, __shfl_xor_sync(0xffffffffu, mx, o));
        if (lane == 0) sred[wid] = mx;
        __syncthreads();                                   // (1)
        if (wid == 0) {
            float m = (lane < NTHREADS / 32) ? sred[lane] : -1e30f;
#pragma unroll
            for (int o = 16; o; o >>= 1)
                m = fmaxf(m, __shfl_xor_sync(0xffffffffu, m, o));
            if (lane == 0) sred[64] = m;
        }
        __syncthreads();                                   // (2)
        const float M = sred[64];

        // ---- exp + local inclusive prefix -------------------------------
        float run = 0.0f;
#pragma unroll
        for (int j = 0; j < EPT; j++) {
            run += __expf(lw[j] - M);
            lw[j] = run;                 // now the local inclusive prefix
        }
        const float ts = run;

        // ---- block scan of per-thread sums ------------------------------
        float sc = ts;
#pragma unroll
        for (int o = 1; o < 32; o <<= 1) {
            float q = __shfl_up_sync(0xffffffffu, sc, o);
            if (lane >= o) sc += q;
        }
        if (lane == 31) sred[wid] = sc;   // warp total
        __syncthreads();                                   // (3)
        if (wid == 0) {
            float v = (lane < NTHREADS / 32) ? sred[lane] : 0.0f;
            float s = v;
#pragma unroll
            for (int o = 1; o < 32; o <<= 1) {
                float q = __shfl_up_sync(0xffffffffu, s, o);
                if (lane >= o) s += q;
            }
            sred[32 + lane] = s - v;      // exclusive warp offset
            if (lane == 31) sred[65] = s; // grand total
        }
        __syncthreads();                                   // (4)
        const float off = sred[32 + wid] + (sc - ts);  // thread's exclusive prefix
        const float total = sred[65];

        // ---- write cdf + bucket table -----------------------------------
        const float scale = (float)KP / total;
        {
            float4* c4 = (float4*)(scdf + kbase);
#pragma unroll
            for (int q = 0; q < EPT / 4; q++) {
                float4 v;
                v.x = off + lw[4*q+0];
                v.y = off + lw[4*q+1];
                v.z = off + lw[4*q+2];
                v.w = off + lw[4*q+3];
                c4[q] = v;
            }
        }
        // Element i covers buckets (floor(S[i-1]*scale), floor(S[i]*scale)];
        // ranges tile [0, KP-1] exactly, so no table init needed.
        float prev = off;
#pragma unroll
        for (int j = 0; j < EPT; j++) {
            float Si = off + lw[j];
            int b0 = (kbase + j == 0) ? -1 : (int)(prev * scale);
            int b1 = (int)(Si * scale);
            if (b1 > KP - 1) b1 = KP - 1;
            for (int b = b0 + 1; b <= b1; b++) sb[b] = (unsigned short)(kbase + j);
            prev = Si;
        }
        __syncthreads();                                   // (5)

        // ---- searchsorted via bucket + short linear scan, then gather ---
        float nw[EPT];
#pragma unroll
        for (int j = 0; j < EPT; j++) {
            float uu = uv[j];
            int b = (int)(uu * (float)KP);
            if (b > KP - 1) b = KP - 1;
            int i = sb[b];
            float target = uu * total;  // search unnormalized cumsum
            while (i < KP - 1 && scdf[i] < target) i++;
            nw[j] = sw[i];              // gather old w
        }
        __syncthreads();                                   // (6) all gathers done
#pragma unroll
        for (int j = 0; j < EPT; j++) {
            sw[kbase + j] = nw[j];
            wr[j] = nw[j];
        }
        // (no barrier needed here: next read of sw is after (5) of step t+1)

        // ---- accumulate lme (thread 0) ----------------------------------
        if (tid == 0) {
            // lme = M + log(total) - logK - 0.5*log(2*pi) - 0.5*x^2
            acc += (double)(M + logf(total)
                            - 9.010913347279288f        // log(8192)
                            - 0.5f * 1.8378770664093453f)
                   - 0.5 * (double)xt * (double)xt;
        }
    }

    if (tid == 0) out[0] = (float)acc;
}

// ---------------------------------------------------------------------------
extern "C" void kernel_launch(void* const* d_in, const int* in_sizes, int n_in,
                              void* d_out, int out_size) {
    const float* x  = (const float*)d_in[0];   // [T]
    const float* w0 = (const float*)d_in[1];   // [K]
    const float* z  = (const float*)d_in[2];   // [K, T]
    const float* u  = (const float*)d_in[3];   // [T, K]
    float* out = (float*)d_out;

    dim3 tb(32, 8);
    dim3 tg(TT / 32, KP / 32);
    transpose_kernel<<<tg, tb>>>(z);

    const size_t smem = (size_t)2 * KP * sizeof(float)
                      + (size_t)KP * sizeof(unsigned short)
                      + 96 * sizeof(float);
    cudaFuncSetAttribute(smc_kernel,
                         cudaFuncAttributeMaxDynamicSharedMemorySize, (int)smem);
    smc_kernel<<<1, NTHREADS, smem>>>(x, w0, u, out);
}